// round 16
// baseline (speedup 1.0000x reference)
#include <cuda_runtime.h>
#include <cuda_bf16.h>
#include <mma.h>
#include <cstdint>
#include <cstddef>

using namespace nvcuda;

#define NCELLS 50000
#define MPAD   50048
#define GDIM   2000
#define H1DIM  512
#define DDIM   128
#define CDIM   128
#define H2DIM  256
#define NPAD45 2048
#define EEDGES 800000
#define NBATCH 4
#define BN_EPS 1e-5f

typedef unsigned long long ull;

// ---------------- device scratch ----------------
__device__ __align__(16) float g_inv_row[NCELLS];
__device__ __align__(16) float g_preact1[(size_t)NCELLS * H1DIM];
__device__ __align__(16) float g_preact2[(size_t)NCELLS * DDIM];
__device__ __align__(16) float g_z[(size_t)NCELLS * DDIM];
__device__ __align__(16) float g_agg[(size_t)NCELLS * DDIM];
__device__ __align__(16) float g_cnt[NCELLS];
__device__ __align__(16) float g_colsum1[H1DIM];
__device__ __align__(16) float g_colsq1[H1DIM];
__device__ __align__(16) float g_a1[H1DIM];
__device__ __align__(16) float g_c1[H1DIM];
__device__ __align__(16) float g_colsum2[DDIM];
__device__ __align__(16) float g_colsq2[DDIM];
__device__ __align__(16) float g_a2[DDIM];
__device__ __align__(16) float g_c2[DDIM];
__device__ int g_e64;
__device__ int g_bad1;
__device__ int g_bad45;

// preconverted bf16 split operands
__device__ __align__(16) __nv_bfloat16 g_xhi[(size_t)MPAD * GDIM];
__device__ __align__(16) __nv_bfloat16 g_xlo[(size_t)MPAD * GDIM];
__device__ __align__(16) __nv_bfloat16 g_w1hi[(size_t)H1DIM * GDIM];
__device__ __align__(16) __nv_bfloat16 g_w1lo[(size_t)H1DIM * GDIM];
__device__ __align__(16) __nv_bfloat16 g_h2hi[(size_t)MPAD * H2DIM];
__device__ __align__(16) __nv_bfloat16 g_h2lo[(size_t)MPAD * H2DIM];
__device__ __align__(16) __nv_bfloat16 g_wshi[(size_t)NPAD45 * H2DIM];
__device__ __align__(16) __nv_bfloat16 g_wslo[(size_t)NPAD45 * H2DIM];
__device__ __align__(16) __nv_bfloat16 g_wdhi[(size_t)NPAD45 * H2DIM];
__device__ __align__(16) __nv_bfloat16 g_wdlo[(size_t)NPAD45 * H2DIM];

__device__ __forceinline__ float4 f4zero() { return make_float4(0.f, 0.f, 0.f, 0.f); }

__device__ __forceinline__ void split2(float a, float b, uint32_t& h, uint32_t& l) {
    __nv_bfloat16 ha = __float2bfloat16_rn(a);
    __nv_bfloat16 hb = __float2bfloat16_rn(b);
    __nv_bfloat16 la = __float2bfloat16_rn(a - __bfloat162float(ha));
    __nv_bfloat16 lb = __float2bfloat16_rn(b - __bfloat162float(hb));
    h = ((uint32_t)__bfloat16_as_ushort(hb) << 16) | (uint32_t)__bfloat16_as_ushort(ha);
    l = ((uint32_t)__bfloat16_as_ushort(lb) << 16) | (uint32_t)__bfloat16_as_ushort(la);
}

__device__ __forceinline__ void split8(const float* v, uint4& oh, uint4& ol) {
    split2(v[0], v[1], oh.x, ol.x);
    split2(v[2], v[3], oh.y, ol.y);
    split2(v[4], v[5], oh.z, ol.z);
    split2(v[6], v[7], oh.w, ol.w);
}

__device__ __forceinline__ uint32_t smem_u32(const void* p) {
    uint32_t a;
    asm("{ .reg .u64 t; cvta.to.shared.u64 t, %1; cvt.u32.u64 %0, t; }" : "=r"(a) : "l"(p));
    return a;
}
#define CP16(sa, gp) asm volatile("cp.async.cg.shared.global [%0], [%1], 16;" :: "r"(sa), "l"(gp))
#define CP_COMMIT()  asm volatile("cp.async.commit_group;" ::: "memory")

// ---------------- small kernels ----------------
__global__ void k_prep(const float* __restrict__ disp, float* __restrict__ out_rate) {
    int i = blockIdx.x * 256 + threadIdx.x;
    if (i < GDIM)  out_rate[i] = expf(disp[i]);
    if (i < H1DIM) { g_colsum1[i] = 0.f; g_colsq1[i] = 0.f; }
    if (i < DDIM)  { g_colsum2[i] = 0.f; g_colsq2[i] = 0.f; }
    if (i == 0 && blockIdx.x == 0) { g_bad1 = 0; g_bad45 = 0; }
}

__global__ void k_rowsum(const float* __restrict__ x) {
    const int row = blockIdx.x;
    const float* xr = x + (size_t)row * GDIM;
    float s = 0.f;
    for (int i = threadIdx.x * 4; i < GDIM; i += 128 * 4) {
        float4 v = *(const float4*)(xr + i);
        s += (v.x + v.y) + (v.z + v.w);
    }
    #pragma unroll
    for (int o = 16; o; o >>= 1) s += __shfl_xor_sync(0xffffffffu, s, o);
    __shared__ float sm[4];
    if ((threadIdx.x & 31) == 0) sm[threadIdx.x >> 5] = s;
    __syncthreads();
    if (threadIdx.x == 0) g_inv_row[row] = 10000.0f / ((sm[0] + sm[1]) + (sm[2] + sm[3]));
}

__global__ void k_detect(const int* __restrict__ ei) {
    if (threadIdx.x == 0 && blockIdx.x == 0) {
        long long s = 0;
        for (int i = 1; i < 2048; i += 2) s += ei[i];
        g_e64 = (s == 0) ? 1 : 0;
    }
}

// x_norm (inv_row folded) -> bf16 hi/lo [MPAD x GDIM]
__global__ void k_conv_x(const float* __restrict__ x) {
    const int m = blockIdx.x;
    const int c = threadIdx.x * 8;
    if (c >= GDIM) return;
    float v[8];
    if (m < NCELLS) {
        const float inv = g_inv_row[m];
        float4 u0 = *(const float4*)(x + (size_t)m * GDIM + c);
        float4 u1 = *(const float4*)(x + (size_t)m * GDIM + c + 4);
        v[0]=u0.x*inv; v[1]=u0.y*inv; v[2]=u0.z*inv; v[3]=u0.w*inv;
        v[4]=u1.x*inv; v[5]=u1.y*inv; v[6]=u1.z*inv; v[7]=u1.w*inv;
    } else {
        #pragma unroll
        for (int j = 0; j < 8; j++) v[j] = 0.f;
    }
    uint4 oh, ol;
    split8(v, oh, ol);
    *(uint4*)(g_xhi + (size_t)m * GDIM + c) = oh;
    *(uint4*)(g_xlo + (size_t)m * GDIM + c) = ol;
}

__global__ void k_conv_w1(const float* __restrict__ w) {
    const int m = blockIdx.x;
    const int c = threadIdx.x * 8;
    if (c >= GDIM) return;
    float v[8];
    float4 u0 = *(const float4*)(w + (size_t)m * GDIM + c);
    float4 u1 = *(const float4*)(w + (size_t)m * GDIM + c + 4);
    v[0]=u0.x; v[1]=u0.y; v[2]=u0.z; v[3]=u0.w; v[4]=u1.x; v[5]=u1.y; v[6]=u1.z; v[7]=u1.w;
    uint4 oh, ol;
    split8(v, oh, ol);
    *(uint4*)(g_w1hi + (size_t)m * GDIM + c) = oh;
    *(uint4*)(g_w1lo + (size_t)m * GDIM + c) = ol;
}

__global__ void k_conv_h2(const float* __restrict__ xz, const float* __restrict__ zu) {
    const int m = blockIdx.x * 8 + (threadIdx.x >> 5);
    const int c = (threadIdx.x & 31) * 8;
    float v[8];
    if (m < NCELLS) {
        const float* src = (c < CDIM) ? (xz + (size_t)m * CDIM + c) : (zu + (size_t)m * DDIM + (c - CDIM));
        float4 u0 = *(const float4*)src;
        float4 u1 = *(const float4*)(src + 4);
        v[0]=u0.x; v[1]=u0.y; v[2]=u0.z; v[3]=u0.w; v[4]=u1.x; v[5]=u1.y; v[6]=u1.z; v[7]=u1.w;
    } else {
        #pragma unroll
        for (int j = 0; j < 8; j++) v[j] = 0.f;
    }
    uint4 oh, ol;
    split8(v, oh, ol);
    *(uint4*)(g_h2hi + (size_t)m * H2DIM + c) = oh;
    *(uint4*)(g_h2lo + (size_t)m * H2DIM + c) = ol;
}

__global__ void k_conv_w256(const float* __restrict__ w, __nv_bfloat16* __restrict__ ohi,
                            __nv_bfloat16* __restrict__ olo) {
    const int m = blockIdx.x * 8 + (threadIdx.x >> 5);
    const int c = (threadIdx.x & 31) * 8;
    float v[8];
    if (m < GDIM) {
        float4 u0 = *(const float4*)(w + (size_t)m * H2DIM + c);
        float4 u1 = *(const float4*)(w + (size_t)m * H2DIM + c + 4);
        v[0]=u0.x; v[1]=u0.y; v[2]=u0.z; v[3]=u0.w; v[4]=u1.x; v[5]=u1.y; v[6]=u1.z; v[7]=u1.w;
    } else {
        #pragma unroll
        for (int j = 0; j < 8; j++) v[j] = 0.f;
    }
    uint4 oh, ol;
    split8(v, oh, ol);
    *(uint4*)(ohi + (size_t)m * H2DIM + c) = oh;
    *(uint4*)(olo + (size_t)m * H2DIM + c) = ol;
}

__global__ void k_colstats() {
    const int r0 = blockIdx.x * 128;
    const int t = threadIdx.x;
    float s0 = 0.f, q0 = 0.f, s1 = 0.f, q1 = 0.f;
    for (int r = 0; r < 128; r++) {
        const int m = r0 + r;
        if (m >= NCELLS) break;
        float v0 = g_preact1[(size_t)m * H1DIM + t];
        float v1 = g_preact1[(size_t)m * H1DIM + t + 256];
        s0 += v0; q0 += v0 * v0; s1 += v1; q1 += v1 * v1;
    }
    atomicAdd(&g_colsum1[t], s0);       atomicAdd(&g_colsq1[t], q0);
    atomicAdd(&g_colsum1[t + 256], s1); atomicAdd(&g_colsq1[t + 256], q1);
}

__global__ void k_fin1(const float* __restrict__ g, const float* __restrict__ be) {
    int i = threadIdx.x;
    float mu  = g_colsum1[i] * (1.0f / NCELLS);
    float var = g_colsq1[i] * (1.0f / NCELLS) - mu * mu;
    float a = g[i] * rsqrtf(var + BN_EPS);
    g_a1[i] = a;
    g_c1[i] = be[i] - mu * a;
}

__global__ void k_fin2(const float* __restrict__ g, const float* __restrict__ be) {
    int i = threadIdx.x;
    float mu  = g_colsum2[i] * (1.0f / NCELLS);
    float var = g_colsq2[i] * (1.0f / NCELLS) - mu * mu;
    float a = g[i] * rsqrtf(var + BN_EPS);
    g_a2[i] = a;
    g_c2[i] = be[i] - mu * a;
}

__global__ void k_zagg() {
    size_t idx = (size_t)blockIdx.x * 256 + threadIdx.x;
    if (idx < (size_t)NCELLS * DDIM) {
        int c = (int)(idx & 127);
        g_z[idx] = fmaxf(fmaf(g_a2[c], g_preact2[idx], g_c2[c]), 0.f);
        g_agg[idx] = 0.f;
        if (idx < NCELLS) g_cnt[idx] = 0.f;
    }
}

__global__ void k_scatter(const void* __restrict__ eiv) {
    const unsigned int idx = blockIdx.x * 256 + threadIdx.x;
    const unsigned int e = idx >> 5;
    const int c = (idx & 31) << 2;
    long long s, d;
    if (g_e64) {
        const long long* ei = (const long long*)eiv;
        s = ei[e]; d = ei[EEDGES + e];
    } else {
        const int* ei = (const int*)eiv;
        s = ei[e]; d = ei[EEDGES + e];
    }
    float4 v = *(const float4*)(g_z + (size_t)s * DDIM + c);
    float* p = g_agg + (size_t)d * DDIM + c;
    asm volatile("red.global.add.v4.f32 [%0], {%1, %2, %3, %4};"
                 :: "l"(p), "f"(v.x), "f"(v.y), "f"(v.z), "f"(v.w) : "memory");
    if ((idx & 31) == 0) atomicAdd(&g_cnt[d], 1.0f);
}

__global__ void k_invcnt() {
    int i = blockIdx.x * 256 + threadIdx.x;
    if (i < NCELLS) g_cnt[i] = 1.0f / fmaxf(g_cnt[i], 1.0f);
}

__global__ void k_batch(const float* __restrict__ zu, const float* __restrict__ Wb,
                        const float* __restrict__ bb, float* __restrict__ out) {
    const int lane = threadIdx.x & 31;
    const int row = blockIdx.x * 8 + (threadIdx.x >> 5);
    if (row >= NCELLS) return;
    float4 zv = *(const float4*)(zu + (size_t)row * DDIM + lane * 4);
    float p[NBATCH];
    #pragma unroll
    for (int nb = 0; nb < NBATCH; nb++) {
        float4 w = *(const float4*)(Wb + nb * DDIM + lane * 4);
        p[nb] = zv.x * w.x + zv.y * w.y + zv.z * w.z + zv.w * w.w;
    }
    #pragma unroll
    for (int nb = 0; nb < NBATCH; nb++) {
        #pragma unroll
        for (int o = 16; o; o >>= 1) p[nb] += __shfl_xor_sync(0xffffffffu, p[nb], o);
    }
    if (lane == 0) {
        #pragma unroll
        for (int nb = 0; nb < NBATCH; nb++)
            out[(size_t)row * NBATCH + nb] = p[nb] + bb[nb];
    }
}

// -------- verification kernels --------
__global__ void k_check1(const float* __restrict__ x, const float* __restrict__ W1,
                         const float* __restrict__ b1) {
    const int t = threadIdx.x;
    const int m = (t * 19373) % NCELLS;
    const int n = (t * 131) % H1DIM;
    const float inv = g_inv_row[m];
    float s = 0.f;
    const float* xp = x + (size_t)m * GDIM;
    const float* wp = W1 + (size_t)n * GDIM;
    for (int k = 0; k < GDIM; k++) s += xp[k] * wp[k];
    const float ref = s * inv + b1[n];
    const float got = g_preact1[(size_t)m * H1DIM + n];
    if (fabsf(got - ref) > 1e-2f * (fabsf(ref) + 1.0f)) g_bad1 = 1;
}

__global__ void k_check45(const float* __restrict__ xz, const float* __restrict__ zu,
                          const float* __restrict__ Ws, const float* __restrict__ bs,
                          const float* __restrict__ ps) {
    const int t = threadIdx.x;
    const int m = (t * 19373) % NCELLS;
    const int n = (t * 131) % GDIM;
    float s = 0.f;
    const float* w0 = Ws + (size_t)n * H2DIM;
    const float* x0 = xz + (size_t)m * CDIM;
    const float* z0 = zu + (size_t)m * DDIM;
    for (int k = 0; k < CDIM; k++) s += x0[k] * w0[k];
    for (int k = 0; k < DDIM; k++) s += z0[k] * w0[CDIM + k];
    const float ref = expf(s + bs[n]);
    const float got = ps[(size_t)m * GDIM + n];
    if (fabsf(got - ref) > 3e-2f * (fabsf(ref) + 1e-6f)) g_bad45 = 1;
}

// ============ WMMA bf16x3 GEMM: pre-split operands + cp.async mainloop ============
// smem: 2 bufs x 4 tiles (Ahi,Alo,Bhi,Blo) x [128][stride 24] bf16 = 49152 B.
// Operands pre-padded: A rows to MPAD (zeros), B rows to >= grid cover (zeros).
#define WG_STR  24
#define WG_TILE (128 * WG_STR)

template<int KDIM, int NVALID, int LDOUT, int EPI>
__global__ void __launch_bounds__(256)
k_wgemm3(const __nv_bfloat16* __restrict__ Ahi, const __nv_bfloat16* __restrict__ Alo,
         const __nv_bfloat16* __restrict__ Bhi, const __nv_bfloat16* __restrict__ Blo,
         const float* __restrict__ bias, float* __restrict__ out) {
    __shared__ __align__(256) __nv_bfloat16 smt[2][4][WG_TILE];   // 49152 bytes

    const int tid = threadIdx.x, lane = tid & 31, wid = tid >> 5;
    const int m0 = blockIdx.x * 128, n0 = blockIdx.y * 128;
    const int wm = (wid >> 2) * 64;
    const int wn = (wid & 3) * 32;

    wmma::fragment<wmma::accumulator, 16, 16, 16, float> acc[4][2];
    #pragma unroll
    for (int mf = 0; mf < 4; mf++)
        #pragma unroll
        for (int nf = 0; nf < 2; nf++)
            wmma::fill_fragment(acc[mf][nf], 0.0f);

    const int r_ = tid >> 1;
    const int k_ = (tid & 1) * 8;
    const uint32_t so2 = (uint32_t)((r_ * WG_STR + k_) * 2);      // byte offset in tile
    const uint32_t sbase = smem_u32(smt);
    const __nv_bfloat16* pAh = Ahi + (size_t)(m0 + r_) * KDIM + k_;
    const __nv_bfloat16* pAl = Alo + (size_t)(m0 + r_) * KDIM + k_;
    const __nv_bfloat16* pBh = Bhi + (size_t)(n0 + r_) * KDIM + k_;
    const __nv_bfloat16* pBl = Blo + (size_t)(n0 + r_) * KDIM + k_;

#define WG_ISSUE(kb, buf) do { \
    const uint32_t b0 = sbase + (uint32_t)((buf) * 4 * WG_TILE * 2) + so2; \
    CP16(b0,                    pAh + (kb)); \
    CP16(b0 + WG_TILE * 2,      pAl + (kb)); \
    CP16(b0 + 2 * WG_TILE * 2,  pBh + (kb)); \
    CP16(b0 + 3 * WG_TILE * 2,  pBl + (kb)); \
    CP_COMMIT(); \
} while (0)

    constexpr int NKC = KDIM / 16;
    WG_ISSUE(0, 0);

    for (int kc = 0; kc < NKC; kc++) {
        const int buf = kc & 1;
        if (kc + 1 < NKC) {
            WG_ISSUE((kc + 1) * 16, buf ^ 1);
            asm volatile("cp.async.wait_group 1;" ::: "memory");
        } else {
            asm volatile("cp.async.wait_group 0;" ::: "memory");
        }
        __syncthreads();

        wmma::fragment<wmma::matrix_b, 16, 16, 16, __nv_bfloat16, wmma::col_major> bh[2], bl[2];
        #pragma unroll
        for (int nf = 0; nf < 2; nf++) {
            wmma::load_matrix_sync(bh[nf], &smt[buf][2][(wn + nf * 16) * WG_STR], WG_STR);
            wmma::load_matrix_sync(bl[nf], &smt[buf][3][(wn + nf * 16) * WG_STR], WG_STR);
        }
        #pragma unroll
        for (int mf = 0; mf < 4; mf++) {
            wmma::fragment<wmma::matrix_a, 16, 16, 16, __nv_bfloat16, wmma::row_major> ah, al;
            wmma::load_matrix_sync(ah, &smt[buf][0][(wm + mf * 16) * WG_STR], WG_STR);
            wmma::load_matrix_sync(al, &smt[buf][1][(wm + mf * 16) * WG_STR], WG_STR);
            #pragma unroll
            for (int nf = 0; nf < 2; nf++) {
                wmma::mma_sync(acc[mf][nf], ah, bh[nf], acc[mf][nf]);
                wmma::mma_sync(acc[mf][nf], ah, bl[nf], acc[mf][nf]);
                wmma::mma_sync(acc[mf][nf], al, bh[nf], acc[mf][nf]);
            }
        }
        __syncthreads();
    }

    // ---- epilogue ----
    float* cs = (float*)smt + wid * (16 * 36);
    const int col = n0 + wn + lane;
    const bool cok = (col < NVALID);
    const float bv = cok ? bias[col] : 0.f;

    #pragma unroll
    for (int mf = 0; mf < 4; mf++) {
        wmma::store_matrix_sync(cs,      acc[mf][0], 36, wmma::mem_row_major);
        wmma::store_matrix_sync(cs + 16, acc[mf][1], 36, wmma::mem_row_major);
        __syncwarp();
        #pragma unroll
        for (int r = 0; r < 16; r++) {
            const int m = m0 + wm + mf * 16 + r;
            if (m < NCELLS && cok) {
                float v = cs[r * 36 + lane] + bv;
                if (EPI == 1) v = expf(v);
                out[(size_t)m * LDOUT + col] = v;
            }
        }
        __syncwarp();
    }
#undef WG_ISSUE
}

// ---------------- SIMT GEMM (all modes; gated fallback for 1/4/5) ----------------
template<int MODE>
__device__ __forceinline__ float4 fetchA(const float* __restrict__ Aa,
                                         const float* __restrict__ Ab,
                                         int m, int k) {
    if constexpr (MODE == 1) {
        return *(const float4*)(Aa + (size_t)m * GDIM + k);
    } else if constexpr (MODE == 2) {
        float4 v = *(const float4*)(g_preact1 + (size_t)m * H1DIM + k);
        float4 a = *(const float4*)(g_a1 + k);
        float4 c = *(const float4*)(g_c1 + k);
        v.x = fmaxf(fmaf(a.x, v.x, c.x), 0.f);
        v.y = fmaxf(fmaf(a.y, v.y, c.y), 0.f);
        v.z = fmaxf(fmaf(a.z, v.z, c.z), 0.f);
        v.w = fmaxf(fmaf(a.w, v.w, c.w), 0.f);
        return v;
    } else if constexpr (MODE == 3) {
        const int seg = k >> 7, loc = k & 127;
        if (seg == 0) {
            float4 v = *(const float4*)(g_agg + (size_t)m * DDIM + loc);
            const float ic = g_cnt[m];
            v.x *= ic; v.y *= ic; v.z *= ic; v.w *= ic;
            return v;
        } else if (seg == 1) {
            return *(const float4*)(g_z + (size_t)m * DDIM + loc);
        } else {
            return *(const float4*)(Aa + (size_t)m * CDIM + loc);
        }
    } else {
        const int seg = k >> 7, loc = k & 127;
        if (seg == 0) return *(const float4*)(Aa + (size_t)m * CDIM + loc);
        return *(const float4*)(Ab + (size_t)m * DDIM + loc);
    }
}

template<int MODE, int NDIM>
__device__ __forceinline__ float4 fetchB(const float* __restrict__ Ba,
                                         const float* __restrict__ Bb,
                                         const float* __restrict__ Bc,
                                         int n, int k) {
    if constexpr (MODE == 1) {
        return *(const float4*)(Ba + (size_t)n * GDIM + k);
    } else if constexpr (MODE == 2) {
        return *(const float4*)(Ba + (size_t)n * H1DIM + k);
    } else if constexpr (MODE == 3) {
        const int seg = k >> 7, loc = k & 127;
        if (seg == 0) return *(const float4*)(Ba + (size_t)n * DDIM + loc);
        if (seg == 1) return *(const float4*)(Bb + (size_t)n * DDIM + loc);
        float4 v = *(const float4*)(Bc + (size_t)n * CDIM + loc);
        v.x = -v.x; v.y = -v.y; v.z = -v.z; v.w = -v.w;
        return v;
    } else {
        if (n >= NDIM) return f4zero();
        return *(const float4*)(Ba + (size_t)n * (CDIM + DDIM) + k);
    }
}

template<int MODE, int NDIM, int KDIM, bool GATED>
__global__ void __launch_bounds__(256, 2)
k_gemm(const float* __restrict__ Aa, const float* __restrict__ Ab,
       const float* __restrict__ Ba, const float* __restrict__ Bb,
       const float* __restrict__ Bc,
       const float* __restrict__ bias, float* __restrict__ Cout) {
    if (GATED) {
        const int bad = (MODE == 1) ? g_bad1 : g_bad45;
        if (bad == 0) return;
    }
    const int tid = threadIdx.x;
    const int tx = tid & 15, ty = tid >> 4;
    const int m0 = blockIdx.x * 128;
    const int n0 = blockIdx.y * 128;

    __shared__ float As[2][16][132];
    __shared__ float Bs[2][16][132];

    ull acc[8][4];
    #pragma unroll
    for (int i = 0; i < 8; i++)
        #pragma unroll
        for (int j = 0; j < 4; j++) acc[i][j] = 0ull;

    const int lr0 = tid >> 2;
    const int lr1 = lr0 + 64;
    const int lk  = (tid & 3) << 2;

    float4 ra0, ra1, rb0, rb1;
    {
        const int ma = m0 + lr0, mb = m0 + lr1;
        ra0 = (ma < NCELLS) ? fetchA<MODE>(Aa, Ab, ma, lk) : f4zero();
        ra1 = (mb < NCELLS) ? fetchA<MODE>(Aa, Ab, mb, lk) : f4zero();
        rb0 = fetchB<MODE, NDIM>(Ba, Bb, Bc, n0 + lr0, lk);
        rb1 = fetchB<MODE, NDIM>(Ba, Bb, Bc, n0 + lr1, lk);
    }
    As[0][lk+0][lr0] = ra0.x; As[0][lk+1][lr0] = ra0.y; As[0][lk+2][lr0] = ra0.z; As[0][lk+3][lr0] = ra0.w;
    As[0][lk+0][lr1] = ra1.x; As[0][lk+1][lr1] = ra1.y; As[0][lk+2][lr1] = ra1.z; As[0][lk+3][lr1] = ra1.w;
    Bs[0][lk+0][lr0] = rb0.x; Bs[0][lk+1][lr0] = rb0.y; Bs[0][lk+2][lr0] = rb0.z; Bs[0][lk+3][lr0] = rb0.w;
    Bs[0][lk+0][lr1] = rb1.x; Bs[0][lk+1][lr1] = rb1.y; Bs[0][lk+2][lr1] = rb1.z; Bs[0][lk+3][lr1] = rb1.w;
    __syncthreads();

    constexpr int NKT = KDIM / 16;
    for (int kt = 0; kt < NKT; ++kt) {
        const int cur = kt & 1;
        if (kt + 1 < NKT) {
            const int gk = (kt + 1) * 16 + lk;
            const int ma = m0 + lr0, mb = m0 + lr1;
            ra0 = (ma < NCELLS) ? fetchA<MODE>(Aa, Ab, ma, gk) : f4zero();
            ra1 = (mb < NCELLS) ? fetchA<MODE>(Aa, Ab, mb, gk) : f4zero();
            rb0 = fetchB<MODE, NDIM>(Ba, Bb, Bc, n0 + lr0, gk);
            rb1 = fetchB<MODE, NDIM>(Ba, Bb, Bc, n0 + lr1, gk);
        }
        #pragma unroll
        for (int kk = 0; kk < 16; ++kk) {
            float4 a0 = *(const float4*)&As[cur][kk][ty * 8];
            float4 a1 = *(const float4*)&As[cur][kk][ty * 8 + 4];
            const ull* bq = (const ull*)&Bs[cur][kk][tx * 8];
            ull bp[4];
            bp[0] = bq[0]; bp[1] = bq[1]; bp[2] = bq[2]; bp[3] = bq[3];
            const float av[8] = {a0.x, a0.y, a0.z, a0.w, a1.x, a1.y, a1.z, a1.w};
            ull ap[8];
            #pragma unroll
            for (int i = 0; i < 8; i++)
                asm("mov.b64 %0, {%1, %1};" : "=l"(ap[i]) : "f"(av[i]));
            #pragma unroll
            for (int i = 0; i < 8; i++)
                #pragma unroll
                for (int j = 0; j < 4; j++)
                    asm("fma.rn.f32x2 %0, %1, %2, %0;" : "+l"(acc[i][j]) : "l"(ap[i]), "l"(bp[j]));
        }
        if (kt + 1 < NKT) {
            const int nb = cur ^ 1;
            As[nb][lk+0][lr0] = ra0.x; As[nb][lk+1][lr0] = ra0.y; As[nb][lk+2][lr0] = ra0.z; As[nb][lk+3][lr0] = ra0.w;
            As[nb][lk+0][lr1] = ra1.x; As[nb][lk+1][lr1] = ra1.y; As[nb][lk+2][lr1] = ra1.z; As[nb][lk+3][lr1] = ra1.w;
            Bs[nb][lk+0][lr0] = rb0.x; Bs[nb][lk+1][lr0] = rb0.y; Bs[nb][lk+2][lr0] = rb0.z; Bs[nb][lk+3][lr0] = rb0.w;
            Bs[nb][lk+0][lr1] = rb1.x; Bs[nb][lk+1][lr1] = rb1.y; Bs[nb][lk+2][lr1] = rb1.z; Bs[nb][lk+3][lr1] = rb1.w;
        }
        __syncthreads();
    }

    const int nb0 = n0 + tx * 8;
    bool colok = true;
    if constexpr (MODE >= 4) colok = (nb0 < NDIM);

    float bia[8];
    if (colok) {
        #pragma unroll
        for (int j = 0; j < 8; j++) bia[j] = bias[nb0 + j];
    }

    float ssum[8], ssq[8];
    if constexpr (MODE == 2) {
        #pragma unroll
        for (int j = 0; j < 8; j++) { ssum[j] = 0.f; ssq[j] = 0.f; }
    }

    #pragma unroll
    for (int i = 0; i < 8; i++) {
        const int m = m0 + ty * 8 + i;
        if (m >= NCELLS) continue;
        float accf[8];
        #pragma unroll
        for (int j = 0; j < 4; j++)
            asm("mov.b64 {%0, %1}, %2;" : "=f"(accf[2*j]), "=f"(accf[2*j+1]) : "l"(acc[i][j]));
        float vals[8];
        if constexpr (MODE == 1) {
            const float inv = g_inv_row[m];
            #pragma unroll
            for (int j = 0; j < 8; j++) vals[j] = fmaf(accf[j], inv, bia[j]);
            float4* p = (float4*)(g_preact1 + (size_t)m * H1DIM + nb0);
            p[0] = make_float4(vals[0], vals[1], vals[2], vals[3]);
            p[1] = make_float4(vals[4], vals[5], vals[6], vals[7]);
        } else if constexpr (MODE == 2) {
            #pragma unroll
            for (int j = 0; j < 8; j++) {
                float v = accf[j] + bia[j];
                vals[j] = v; ssum[j] += v; ssq[j] += v * v;
            }
            float4* p = (float4*)(g_preact2 + (size_t)m * DDIM + nb0);
            p[0] = make_float4(vals[0], vals[1], vals[2], vals[3]);
            p[1] = make_float4(vals[4], vals[5], vals[6], vals[7]);
        } else if constexpr (MODE == 3) {
            #pragma unroll
            for (int j = 0; j < 8; j++) vals[j] = fmaxf(accf[j] + bia[j], 0.f);
            float4* p = (float4*)(Cout + (size_t)m * DDIM + nb0);
            p[0] = make_float4(vals[0], vals[1], vals[2], vals[3]);
            p[1] = make_float4(vals[4], vals[5], vals[6], vals[7]);
        } else if constexpr (MODE == 4) {
            if (colok) {
                #pragma unroll
                for (int j = 0; j < 8; j++) vals[j] = expf(accf[j] + bia[j]);
                float4* p = (float4*)(Cout + (size_t)m * NDIM + nb0);
                p[0] = make_float4(vals[0], vals[1], vals[2], vals[3]);
                p[1] = make_float4(vals[4], vals[5], vals[6], vals[7]);
            }
        } else {
            if (colok) {
                #pragma unroll
                for (int j = 0; j < 8; j++) vals[j] = accf[j] + bia[j];
                float4* p = (float4*)(Cout + (size_t)m * NDIM + nb0);
                p[0] = make_float4(vals[0], vals[1], vals[2], vals[3]);
                p[1] = make_float4(vals[4], vals[5], vals[6], vals[7]);
            }
        }
    }

    if constexpr (MODE == 2) {
        #pragma unroll
        for (int j = 0; j < 8; j++) {
            atomicAdd(&g_colsum2[nb0 + j], ssum[j]);
            atomicAdd(&g_colsq2[nb0 + j], ssq[j]);
        }
    }
}

// ---------------- launch ----------------
extern "C" void kernel_launch(void* const* d_in, const int* in_sizes, int n_in,
                              void* d_out, int out_size) {
    const float* x_c1 = (const float*)d_in[0];
    const float* x_zc = (const float*)d_in[1];
    const void*  ei   = d_in[2];
    const float* W1  = (const float*)d_in[3];
    const float* b1  = (const float*)d_in[4];
    const float* g1  = (const float*)d_in[5];
    const float* be1 = (const float*)d_in[6];
    const float* W2  = (const float*)d_in[7];
    const float* b2  = (const float*)d_in[8];
    const float* g2  = (const float*)d_in[9];
    const float* be2 = (const float*)d_in[10];
    const float* Wl  = (const float*)d_in[11];
    const float* bl  = (const float*)d_in[12];
    const float* Wr  = (const float*)d_in[13];
    const float* Wc  = (const float*)d_in[14];
    const float* Ws  = (const float*)d_in[15];
    const float* bs  = (const float*)d_in[16];
    const float* Wd  = (const float*)d_in[17];
    const float* bd  = (const float*)d_in[18];
    const float* disp= (const float*)d_in[19];
    const float* Wb  = (const float*)d_in[20];
    const float* bb  = (const float*)d_in[21];

    float* out    = (float*)d_out;
    float* out_zu = out;
    float* out_ps = out_zu + (size_t)NCELLS * DDIM;
    float* out_pr = out_ps + (size_t)NCELLS * GDIM;
    float* out_pd = out_pr + GDIM;
    float* out_bp = out_pd + (size_t)NCELLS * GDIM;

    const int MT = (NCELLS + 127) / 128;  // 391

    k_prep<<<8, 256>>>(disp, out_pr);
    k_rowsum<<<NCELLS, 128>>>(x_c1);
    k_detect<<<1, 32>>>((const int*)ei);

    // conversions for GEMM1
    k_conv_x<<<MPAD, 256>>>(x_c1);
    k_conv_w1<<<H1DIM, 256>>>(W1);

    // GEMM1 tensor (cp.async) + verification + gated SIMT fallback
    k_wgemm3<GDIM, H1DIM, H1DIM, 0><<<dim3(MT, 4), 256>>>(g_xhi, g_xlo, g_w1hi, g_w1lo, b1, g_preact1);
    k_check1<<<1, 256>>>(x_c1, W1, b1);
    k_gemm<1, H1DIM, GDIM, true><<<dim3(MT, 4), 256>>>(x_c1, nullptr, W1, nullptr, nullptr, b1, nullptr);

    k_colstats<<<MT, 256>>>();
    k_fin1<<<1, H1DIM>>>(g1, be1);

    // GEMM2 (SIMT): preact2 + BN2 stats
    k_gemm<2, DDIM, H1DIM, false><<<dim3(MT, 1), 256>>>(nullptr, nullptr, W2, nullptr, nullptr, b2, nullptr);
    k_fin2<<<1, DDIM>>>(g2, be2);

    k_zagg<<<((size_t)NCELLS * DDIM + 255) / 256, 256>>>();
    k_scatter<<<(EEDGES * 32) / 256, 256>>>(ei);
    k_invcnt<<<(NCELLS + 255) / 256, 256>>>();

    // GEMM3 (SIMT): z_unique
    k_gemm<3, DDIM, 384, false><<<dim3(MT, 1), 256>>>(x_zc, nullptr, Wl, Wr, Wc, bl, out_zu);
    k_batch<<<(NCELLS + 7) / 8, 256>>>(out_zu, Wb, bb, out_bp);

    // conversions for GEMM4/5
    k_conv_h2<<<MPAD / 8, 256>>>(x_zc, out_zu);
    k_conv_w256<<<NPAD45 / 8, 256>>>(Ws, g_wshi, g_wslo);
    k_conv_w256<<<NPAD45 / 8, 256>>>(Wd, g_wdhi, g_wdlo);

    // GEMM4/5 tensor (cp.async) + verification + gated SIMT fallbacks
    k_wgemm3<H2DIM, GDIM, GDIM, 1><<<dim3(MT, 16), 256>>>(g_h2hi, g_h2lo, g_wshi, g_wslo, bs, out_ps);
    k_wgemm3<H2DIM, GDIM, GDIM, 0><<<dim3(MT, 16), 256>>>(g_h2hi, g_h2lo, g_wdhi, g_wdlo, bd, out_pd);
    k_check45<<<1, 256>>>(x_zc, out_zu, Ws, bs, out_ps);
    k_gemm<4, GDIM, 256, true><<<dim3(MT, 16), 256>>>(x_zc, out_zu, Ws, nullptr, nullptr, bs, out_ps);
    k_gemm<5, GDIM, 256, true><<<dim3(MT, 16), 256>>>(x_zc, out_zu, Wd, nullptr, nullptr, bd, out_pd);
}

// round 17
// speedup vs baseline: 17.8216x; 17.8216x over previous
#include <cuda_runtime.h>
#include <cuda_bf16.h>
#include <mma.h>
#include <cstdint>
#include <cstddef>

using namespace nvcuda;

#define NCELLS 50000
#define GDIM   2000
#define H1DIM  512
#define DDIM   128
#define CDIM   128
#define H2DIM  256
#define EEDGES 800000
#define NBATCH 4
#define BN_EPS 1e-5f

typedef unsigned long long ull;

// ---------------- device scratch ----------------
__device__ __align__(16) float g_inv_row[NCELLS];
__device__ __align__(16) float g_preact1[(size_t)NCELLS * H1DIM];
__device__ __align__(16) float g_preact2[(size_t)NCELLS * DDIM];
__device__ __align__(16) float g_z[(size_t)NCELLS * DDIM];
__device__ __align__(16) float g_agg[(size_t)NCELLS * DDIM];
__device__ __align__(16) float g_cnt[NCELLS];
__device__ __align__(16) float g_colsum1[H1DIM];
__device__ __align__(16) float g_colsq1[H1DIM];
__device__ __align__(16) float g_a1[H1DIM];
__device__ __align__(16) float g_c1[H1DIM];
__device__ __align__(16) float g_colsum2[DDIM];
__device__ __align__(16) float g_colsq2[DDIM];
__device__ __align__(16) float g_a2[DDIM];
__device__ __align__(16) float g_c2[DDIM];
__device__ int g_e64;
__device__ int g_bad1;
__device__ int g_bad45;

__device__ __forceinline__ float4 f4zero() { return make_float4(0.f, 0.f, 0.f, 0.f); }

// Pack two floats -> bf16-hi pair + bf16-lo pair (register-only).
__device__ __forceinline__ void split2(float a, float b, uint32_t& h, uint32_t& l) {
    __nv_bfloat16 ha = __float2bfloat16_rn(a);
    __nv_bfloat16 hb = __float2bfloat16_rn(b);
    __nv_bfloat16 la = __float2bfloat16_rn(a - __bfloat162float(ha));
    __nv_bfloat16 lb = __float2bfloat16_rn(b - __bfloat162float(hb));
    h = ((uint32_t)__bfloat16_as_ushort(hb) << 16) | (uint32_t)__bfloat16_as_ushort(ha);
    l = ((uint32_t)__bfloat16_as_ushort(lb) << 16) | (uint32_t)__bfloat16_as_ushort(la);
}

__device__ __forceinline__ void split8(const float* v, uint4& oh, uint4& ol) {
    split2(v[0], v[1], oh.x, ol.x);
    split2(v[2], v[3], oh.y, ol.y);
    split2(v[4], v[5], oh.z, ol.z);
    split2(v[6], v[7], oh.w, ol.w);
}

// ---------------- small kernels ----------------
__global__ void k_prep(const float* __restrict__ disp, float* __restrict__ out_rate) {
    int i = blockIdx.x * 256 + threadIdx.x;
    if (i < GDIM)  out_rate[i] = expf(disp[i]);
    if (i < H1DIM) { g_colsum1[i] = 0.f; g_colsq1[i] = 0.f; }
    if (i < DDIM)  { g_colsum2[i] = 0.f; g_colsq2[i] = 0.f; }
    if (i == 0 && blockIdx.x == 0) { g_bad1 = 0; g_bad45 = 0; }
}

__global__ void k_rowsum(const float* __restrict__ x) {
    const int row = blockIdx.x;
    const float* xr = x + (size_t)row * GDIM;
    float s = 0.f;
    for (int i = threadIdx.x * 4; i < GDIM; i += 128 * 4) {
        float4 v = *(const float4*)(xr + i);
        s += (v.x + v.y) + (v.z + v.w);
    }
    #pragma unroll
    for (int o = 16; o; o >>= 1) s += __shfl_xor_sync(0xffffffffu, s, o);
    __shared__ float sm[4];
    if ((threadIdx.x & 31) == 0) sm[threadIdx.x >> 5] = s;
    __syncthreads();
    if (threadIdx.x == 0) g_inv_row[row] = 10000.0f / ((sm[0] + sm[1]) + (sm[2] + sm[3]));
}

__global__ void k_detect(const int* __restrict__ ei) {
    if (threadIdx.x == 0 && blockIdx.x == 0) {
        long long s = 0;
        for (int i = 1; i < 2048; i += 2) s += ei[i];
        g_e64 = (s == 0) ? 1 : 0;
    }
}

// gated: only used when GEMM1 fallback fired (stats from wgemm are then invalid)
__global__ void k_statreset() {
    if (g_bad1 == 0) return;
    int i = threadIdx.x;
    g_colsum1[i] = 0.f;
    g_colsq1[i] = 0.f;
}

__global__ void k_colstats() {
    if (g_bad1 == 0) return;
    const int r0 = blockIdx.x * 128;
    const int t = threadIdx.x;
    float s0 = 0.f, q0 = 0.f, s1 = 0.f, q1 = 0.f;
    for (int r = 0; r < 128; r++) {
        const int m = r0 + r;
        if (m >= NCELLS) break;
        float v0 = g_preact1[(size_t)m * H1DIM + t];
        float v1 = g_preact1[(size_t)m * H1DIM + t + 256];
        s0 += v0; q0 += v0 * v0; s1 += v1; q1 += v1 * v1;
    }
    atomicAdd(&g_colsum1[t], s0);       atomicAdd(&g_colsq1[t], q0);
    atomicAdd(&g_colsum1[t + 256], s1); atomicAdd(&g_colsq1[t + 256], q1);
}

__global__ void k_fin1(const float* __restrict__ g, const float* __restrict__ be) {
    int i = threadIdx.x;
    float mu  = g_colsum1[i] * (1.0f / NCELLS);
    float var = g_colsq1[i] * (1.0f / NCELLS) - mu * mu;
    float a = g[i] * rsqrtf(var + BN_EPS);
    g_a1[i] = a;
    g_c1[i] = be[i] - mu * a;
}

__global__ void k_fin2(const float* __restrict__ g, const float* __restrict__ be) {
    int i = threadIdx.x;
    float mu  = g_colsum2[i] * (1.0f / NCELLS);
    float var = g_colsq2[i] * (1.0f / NCELLS) - mu * mu;
    float a = g[i] * rsqrtf(var + BN_EPS);
    g_a2[i] = a;
    g_c2[i] = be[i] - mu * a;
}

__global__ void k_zagg() {
    size_t idx = (size_t)blockIdx.x * 256 + threadIdx.x;
    if (idx < (size_t)NCELLS * DDIM) {
        int c = (int)(idx & 127);
        g_z[idx] = fmaxf(fmaf(g_a2[c], g_preact2[idx], g_c2[c]), 0.f);
        g_agg[idx] = 0.f;
        if (idx < NCELLS) g_cnt[idx] = 0.f;
    }
}

__global__ void k_scatter(const void* __restrict__ eiv) {
    const unsigned int idx = blockIdx.x * 256 + threadIdx.x;
    const unsigned int e = idx >> 5;
    const int c = (idx & 31) << 2;
    long long s, d;
    if (g_e64) {
        const long long* ei = (const long long*)eiv;
        s = ei[e]; d = ei[EEDGES + e];
    } else {
        const int* ei = (const int*)eiv;
        s = ei[e]; d = ei[EEDGES + e];
    }
    float4 v = *(const float4*)(g_z + (size_t)s * DDIM + c);
    float* p = g_agg + (size_t)d * DDIM + c;
    asm volatile("red.global.add.v4.f32 [%0], {%1, %2, %3, %4};"
                 :: "l"(p), "f"(v.x), "f"(v.y), "f"(v.z), "f"(v.w) : "memory");
    if ((idx & 31) == 0) atomicAdd(&g_cnt[d], 1.0f);
}

__global__ void k_invcnt() {
    int i = blockIdx.x * 256 + threadIdx.x;
    if (i < NCELLS) g_cnt[i] = 1.0f / fmaxf(g_cnt[i], 1.0f);
}

__global__ void k_batch(const float* __restrict__ zu, const float* __restrict__ Wb,
                        const float* __restrict__ bb, float* __restrict__ out) {
    const int lane = threadIdx.x & 31;
    const int row = blockIdx.x * 8 + (threadIdx.x >> 5);
    if (row >= NCELLS) return;
    float4 zv = *(const float4*)(zu + (size_t)row * DDIM + lane * 4);
    float p[NBATCH];
    #pragma unroll
    for (int nb = 0; nb < NBATCH; nb++) {
        float4 w = *(const float4*)(Wb + nb * DDIM + lane * 4);
        p[nb] = zv.x * w.x + zv.y * w.y + zv.z * w.z + zv.w * w.w;
    }
    #pragma unroll
    for (int nb = 0; nb < NBATCH; nb++) {
        #pragma unroll
        for (int o = 16; o; o >>= 1) p[nb] += __shfl_xor_sync(0xffffffffu, p[nb], o);
    }
    if (lane == 0) {
        #pragma unroll
        for (int nb = 0; nb < NBATCH; nb++)
            out[(size_t)row * NBATCH + nb] = p[nb] + bb[nb];
    }
}

// -------- verification kernels: sample dot products, set g_bad flags --------
__global__ void k_check1(const float* __restrict__ x, const float* __restrict__ W1,
                         const float* __restrict__ b1) {
    const int t = threadIdx.x;
    const int m = (t * 19373) % NCELLS;
    const int n = (t * 131) % H1DIM;
    const float inv = g_inv_row[m];
    float s = 0.f;
    const float* xp = x + (size_t)m * GDIM;
    const float* wp = W1 + (size_t)n * GDIM;
    for (int k = 0; k < GDIM; k++) s += xp[k] * wp[k];
    const float ref = s * inv + b1[n];
    const float got = g_preact1[(size_t)m * H1DIM + n];
    if (fabsf(got - ref) > 1e-2f * (fabsf(ref) + 1.0f)) g_bad1 = 1;
}

__global__ void k_check45(const float* __restrict__ xz, const float* __restrict__ zu,
                          const float* __restrict__ Ws, const float* __restrict__ bs,
                          const float* __restrict__ ps) {
    const int t = threadIdx.x;
    const int m = (t * 19373) % NCELLS;
    const int n = (t * 131) % GDIM;
    float s = 0.f;
    const float* w0 = Ws + (size_t)n * H2DIM;
    const float* x0 = xz + (size_t)m * CDIM;
    const float* z0 = zu + (size_t)m * DDIM;
    for (int k = 0; k < CDIM; k++) s += x0[k] * w0[k];
    for (int k = 0; k < DDIM; k++) s += z0[k] * w0[CDIM + k];
    const float ref = expf(s + bs[n]);
    const float got = ps[(size_t)m * GDIM + n];
    if (fabsf(got - ref) > 3e-2f * (fabsf(ref) + 1e-6f)) g_bad45 = 1;
}

// ============ WMMA bf16x3-split GEMM, in-kernel split, stride-24 tiles ============
// Static smem: 2 bufs x 4 tiles (Ahi,Alo,Bhi,Blo) x [128][stride 24] bf16 = 49152 B.
// MODE 1: A = x_c1 (raw), epilogue scales by inv_row then adds bias; also
//         accumulates BN1 column stats (sum / sumsq) via per-thread partials + atomics.
// MODE 4: A = [x_zc | zu], bias in epilogue (+optional exp).
#define WG_STR  24
#define WG_TILE (128 * WG_STR)

template<int MODE, int KDIM, int NVALID, int LDOUT, int EPI>
__global__ void __launch_bounds__(256)
k_wgemm2(const float* __restrict__ A1, const float* __restrict__ A2,
         const float* __restrict__ B,
         const float* __restrict__ bias, float* __restrict__ out) {
    __shared__ __align__(256) __nv_bfloat16 smt[2][4][WG_TILE];   // 49152 bytes

    const int tid = threadIdx.x, lane = tid & 31, wid = tid >> 5;
    const int m0 = blockIdx.x * 128, n0 = blockIdx.y * 128;
    const int wm = (wid >> 2) * 64;
    const int wn = (wid & 3) * 32;

    wmma::fragment<wmma::accumulator, 16, 16, 16, float> acc[4][2];
    #pragma unroll
    for (int mf = 0; mf < 4; mf++)
        #pragma unroll
        for (int nf = 0; nf < 2; nf++)
            wmma::fill_fragment(acc[mf][nf], 0.0f);

    const int r_ = tid >> 1;
    const int k_ = (tid & 1) * 8;
    const int so = r_ * WG_STR + k_;
    const int am = m0 + r_;
    const int bn = n0 + r_;
    const bool aok = (am < NCELLS);
    const bool bok = (MODE == 1) ? true : (bn < GDIM);

    uint4 hA, lA, hB, lB;

#define WG_LOADG(kb) do { \
    float va[8], vb[8]; \
    if (aok) { \
        const float* pa; \
        if (MODE == 1) pa = A1 + (size_t)am * GDIM + (kb) + k_; \
        else { \
            const int kk2 = (kb) + k_; \
            pa = (kk2 < CDIM) ? (A1 + (size_t)am * CDIM + kk2) \
                              : (A2 + (size_t)am * DDIM + (kk2 - CDIM)); \
        } \
        float4 u0 = *(const float4*)pa, u1 = *(const float4*)(pa + 4); \
        va[0]=u0.x; va[1]=u0.y; va[2]=u0.z; va[3]=u0.w; \
        va[4]=u1.x; va[5]=u1.y; va[6]=u1.z; va[7]=u1.w; \
    } else { \
        _Pragma("unroll") for (int j = 0; j < 8; j++) va[j] = 0.f; \
    } \
    if (bok) { \
        const float* pb = B + (size_t)bn * KDIM + (kb) + k_; \
        float4 u0 = *(const float4*)pb, u1 = *(const float4*)(pb + 4); \
        vb[0]=u0.x; vb[1]=u0.y; vb[2]=u0.z; vb[3]=u0.w; \
        vb[4]=u1.x; vb[5]=u1.y; vb[6]=u1.z; vb[7]=u1.w; \
    } else { \
        _Pragma("unroll") for (int j = 0; j < 8; j++) vb[j] = 0.f; \
    } \
    split8(va, hA, lA); \
    split8(vb, hB, lB); \
} while (0)

#define WG_STORES(buf) do { \
    *(uint4*)(&smt[buf][0][so]) = hA; \
    *(uint4*)(&smt[buf][1][so]) = lA; \
    *(uint4*)(&smt[buf][2][so]) = hB; \
    *(uint4*)(&smt[buf][3][so]) = lB; \
} while (0)

    WG_LOADG(0);
    WG_STORES(0);
    __syncthreads();

    constexpr int NKC = KDIM / 16;
    for (int kc = 0; kc < NKC; kc++) {
        const int buf = kc & 1;
        if (kc + 1 < NKC) WG_LOADG((kc + 1) * 16);

        wmma::fragment<wmma::matrix_b, 16, 16, 16, __nv_bfloat16, wmma::col_major> bh[2], bl[2];
        #pragma unroll
        for (int nf = 0; nf < 2; nf++) {
            wmma::load_matrix_sync(bh[nf], &smt[buf][2][(wn + nf * 16) * WG_STR], WG_STR);
            wmma::load_matrix_sync(bl[nf], &smt[buf][3][(wn + nf * 16) * WG_STR], WG_STR);
        }
        #pragma unroll
        for (int mf = 0; mf < 4; mf++) {
            wmma::fragment<wmma::matrix_a, 16, 16, 16, __nv_bfloat16, wmma::row_major> ah, al;
            wmma::load_matrix_sync(ah, &smt[buf][0][(wm + mf * 16) * WG_STR], WG_STR);
            wmma::load_matrix_sync(al, &smt[buf][1][(wm + mf * 16) * WG_STR], WG_STR);
            #pragma unroll
            for (int nf = 0; nf < 2; nf++) {
                wmma::mma_sync(acc[mf][nf], ah, bh[nf], acc[mf][nf]);
                wmma::mma_sync(acc[mf][nf], ah, bl[nf], acc[mf][nf]);
                wmma::mma_sync(acc[mf][nf], al, bh[nf], acc[mf][nf]);
            }
        }
        if (kc + 1 < NKC) WG_STORES(buf ^ 1);
        __syncthreads();
    }

    // ---- epilogue: per-warp smem staging (reuse smt), explicit coordinates ----
    float* cs = (float*)smt + wid * (16 * 36);
    const int col = n0 + wn + lane;
    const bool cok = (col < NVALID);
    const float bv = cok ? bias[col] : 0.f;

    float ssum = 0.f, ssq = 0.f;   // MODE 1 BN stats (this thread owns column `col`)

    #pragma unroll
    for (int mf = 0; mf < 4; mf++) {
        wmma::store_matrix_sync(cs,      acc[mf][0], 36, wmma::mem_row_major);
        wmma::store_matrix_sync(cs + 16, acc[mf][1], 36, wmma::mem_row_major);
        __syncwarp();
        #pragma unroll
        for (int r = 0; r < 16; r++) {
            const int m = m0 + wm + mf * 16 + r;
            if (m < NCELLS && cok) {
                float v = cs[r * 36 + lane];
                if (MODE == 1) {
                    v = fmaf(v, g_inv_row[m], bv);
                    ssum += v; ssq += v * v;
                } else {
                    v = v + bv;
                }
                if (EPI == 1) v = expf(v);
                out[(size_t)m * LDOUT + col] = v;
            }
        }
        __syncwarp();
    }

    if (MODE == 1 && cok) {
        atomicAdd(&g_colsum1[col], ssum);
        atomicAdd(&g_colsq1[col], ssq);
    }
#undef WG_LOADG
#undef WG_STORES
}

// ---------------- SIMT GEMM (all modes; gated fallback for 1/4/5) ----------------
template<int MODE>
__device__ __forceinline__ float4 fetchA(const float* __restrict__ Aa,
                                         const float* __restrict__ Ab,
                                         int m, int k) {
    if constexpr (MODE == 1) {
        return *(const float4*)(Aa + (size_t)m * GDIM + k);
    } else if constexpr (MODE == 2) {
        float4 v = *(const float4*)(g_preact1 + (size_t)m * H1DIM + k);
        float4 a = *(const float4*)(g_a1 + k);
        float4 c = *(const float4*)(g_c1 + k);
        v.x = fmaxf(fmaf(a.x, v.x, c.x), 0.f);
        v.y = fmaxf(fmaf(a.y, v.y, c.y), 0.f);
        v.z = fmaxf(fmaf(a.z, v.z, c.z), 0.f);
        v.w = fmaxf(fmaf(a.w, v.w, c.w), 0.f);
        return v;
    } else if constexpr (MODE == 3) {
        const int seg = k >> 7, loc = k & 127;
        if (seg == 0) {
            float4 v = *(const float4*)(g_agg + (size_t)m * DDIM + loc);
            const float ic = g_cnt[m];
            v.x *= ic; v.y *= ic; v.z *= ic; v.w *= ic;
            return v;
        } else if (seg == 1) {
            return *(const float4*)(g_z + (size_t)m * DDIM + loc);
        } else {
            return *(const float4*)(Aa + (size_t)m * CDIM + loc);
        }
    } else {
        const int seg = k >> 7, loc = k & 127;
        if (seg == 0) return *(const float4*)(Aa + (size_t)m * CDIM + loc);
        return *(const float4*)(Ab + (size_t)m * DDIM + loc);
    }
}

template<int MODE, int NDIM>
__device__ __forceinline__ float4 fetchB(const float* __restrict__ Ba,
                                         const float* __restrict__ Bb,
                                         const float* __restrict__ Bc,
                                         int n, int k) {
    if constexpr (MODE == 1) {
        return *(const float4*)(Ba + (size_t)n * GDIM + k);
    } else if constexpr (MODE == 2) {
        return *(const float4*)(Ba + (size_t)n * H1DIM + k);
    } else if constexpr (MODE == 3) {
        const int seg = k >> 7, loc = k & 127;
        if (seg == 0) return *(const float4*)(Ba + (size_t)n * DDIM + loc);
        if (seg == 1) return *(const float4*)(Bb + (size_t)n * DDIM + loc);
        float4 v = *(const float4*)(Bc + (size_t)n * CDIM + loc);
        v.x = -v.x; v.y = -v.y; v.z = -v.z; v.w = -v.w;
        return v;
    } else {
        if (n >= NDIM) return f4zero();
        return *(const float4*)(Ba + (size_t)n * (CDIM + DDIM) + k);
    }
}

template<int MODE, int NDIM, int KDIM, bool GATED>
__global__ void __launch_bounds__(256, 2)
k_gemm(const float* __restrict__ Aa, const float* __restrict__ Ab,
       const float* __restrict__ Ba, const float* __restrict__ Bb,
       const float* __restrict__ Bc,
       const float* __restrict__ bias, float* __restrict__ Cout) {
    if (GATED) {
        const int bad = (MODE == 1) ? g_bad1 : g_bad45;
        if (bad == 0) return;
    }
    const int tid = threadIdx.x;
    const int tx = tid & 15, ty = tid >> 4;
    const int m0 = blockIdx.x * 128;
    const int n0 = blockIdx.y * 128;

    __shared__ float As[2][16][132];
    __shared__ float Bs[2][16][132];

    ull acc[8][4];
    #pragma unroll
    for (int i = 0; i < 8; i++)
        #pragma unroll
        for (int j = 0; j < 4; j++) acc[i][j] = 0ull;

    const int lr0 = tid >> 2;
    const int lr1 = lr0 + 64;
    const int lk  = (tid & 3) << 2;

    float4 ra0, ra1, rb0, rb1;
    {
        const int ma = m0 + lr0, mb = m0 + lr1;
        ra0 = (ma < NCELLS) ? fetchA<MODE>(Aa, Ab, ma, lk) : f4zero();
        ra1 = (mb < NCELLS) ? fetchA<MODE>(Aa, Ab, mb, lk) : f4zero();
        rb0 = fetchB<MODE, NDIM>(Ba, Bb, Bc, n0 + lr0, lk);
        rb1 = fetchB<MODE, NDIM>(Ba, Bb, Bc, n0 + lr1, lk);
    }
    As[0][lk+0][lr0] = ra0.x; As[0][lk+1][lr0] = ra0.y; As[0][lk+2][lr0] = ra0.z; As[0][lk+3][lr0] = ra0.w;
    As[0][lk+0][lr1] = ra1.x; As[0][lk+1][lr1] = ra1.y; As[0][lk+2][lr1] = ra1.z; As[0][lk+3][lr1] = ra1.w;
    Bs[0][lk+0][lr0] = rb0.x; Bs[0][lk+1][lr0] = rb0.y; Bs[0][lk+2][lr0] = rb0.z; Bs[0][lk+3][lr0] = rb0.w;
    Bs[0][lk+0][lr1] = rb1.x; Bs[0][lk+1][lr1] = rb1.y; Bs[0][lk+2][lr1] = rb1.z; Bs[0][lk+3][lr1] = rb1.w;
    __syncthreads();

    constexpr int NKT = KDIM / 16;
    for (int kt = 0; kt < NKT; ++kt) {
        const int cur = kt & 1;
        if (kt + 1 < NKT) {
            const int gk = (kt + 1) * 16 + lk;
            const int ma = m0 + lr0, mb = m0 + lr1;
            ra0 = (ma < NCELLS) ? fetchA<MODE>(Aa, Ab, ma, gk) : f4zero();
            ra1 = (mb < NCELLS) ? fetchA<MODE>(Aa, Ab, mb, gk) : f4zero();
            rb0 = fetchB<MODE, NDIM>(Ba, Bb, Bc, n0 + lr0, gk);
            rb1 = fetchB<MODE, NDIM>(Ba, Bb, Bc, n0 + lr1, gk);
        }
        #pragma unroll
        for (int kk = 0; kk < 16; ++kk) {
            float4 a0 = *(const float4*)&As[cur][kk][ty * 8];
            float4 a1 = *(const float4*)&As[cur][kk][ty * 8 + 4];
            const ull* bq = (const ull*)&Bs[cur][kk][tx * 8];
            ull bp[4];
            bp[0] = bq[0]; bp[1] = bq[1]; bp[2] = bq[2]; bp[3] = bq[3];
            const float av[8] = {a0.x, a0.y, a0.z, a0.w, a1.x, a1.y, a1.z, a1.w};
            ull ap[8];
            #pragma unroll
            for (int i = 0; i < 8; i++)
                asm("mov.b64 %0, {%1, %1};" : "=l"(ap[i]) : "f"(av[i]));
            #pragma unroll
            for (int i = 0; i < 8; i++)
                #pragma unroll
                for (int j = 0; j < 4; j++)
                    asm("fma.rn.f32x2 %0, %1, %2, %0;" : "+l"(acc[i][j]) : "l"(ap[i]), "l"(bp[j]));
        }
        if (kt + 1 < NKT) {
            const int nb = cur ^ 1;
            As[nb][lk+0][lr0] = ra0.x; As[nb][lk+1][lr0] = ra0.y; As[nb][lk+2][lr0] = ra0.z; As[nb][lk+3][lr0] = ra0.w;
            As[nb][lk+0][lr1] = ra1.x; As[nb][lk+1][lr1] = ra1.y; As[nb][lk+2][lr1] = ra1.z; As[nb][lk+3][lr1] = ra1.w;
            Bs[nb][lk+0][lr0] = rb0.x; Bs[nb][lk+1][lr0] = rb0.y; Bs[nb][lk+2][lr0] = rb0.z; Bs[nb][lk+3][lr0] = rb0.w;
            Bs[nb][lk+0][lr1] = rb1.x; Bs[nb][lk+1][lr1] = rb1.y; Bs[nb][lk+2][lr1] = rb1.z; Bs[nb][lk+3][lr1] = rb1.w;
        }
        __syncthreads();
    }

    const int nb0 = n0 + tx * 8;
    bool colok = true;
    if constexpr (MODE >= 4) colok = (nb0 < NDIM);

    float bia[8];
    if (colok) {
        #pragma unroll
        for (int j = 0; j < 8; j++) bia[j] = bias[nb0 + j];
    }

    float ssum[8], ssq[8];
    if constexpr (MODE == 2) {
        #pragma unroll
        for (int j = 0; j < 8; j++) { ssum[j] = 0.f; ssq[j] = 0.f; }
    }

    #pragma unroll
    for (int i = 0; i < 8; i++) {
        const int m = m0 + ty * 8 + i;
        if (m >= NCELLS) continue;
        float accf[8];
        #pragma unroll
        for (int j = 0; j < 4; j++)
            asm("mov.b64 {%0, %1}, %2;" : "=f"(accf[2*j]), "=f"(accf[2*j+1]) : "l"(acc[i][j]));
        float vals[8];
        if constexpr (MODE == 1) {
            const float inv = g_inv_row[m];
            #pragma unroll
            for (int j = 0; j < 8; j++) vals[j] = fmaf(accf[j], inv, bia[j]);
            float4* p = (float4*)(g_preact1 + (size_t)m * H1DIM + nb0);
            p[0] = make_float4(vals[0], vals[1], vals[2], vals[3]);
            p[1] = make_float4(vals[4], vals[5], vals[6], vals[7]);
        } else if constexpr (MODE == 2) {
            #pragma unroll
            for (int j = 0; j < 8; j++) {
                float v = accf[j] + bia[j];
                vals[j] = v; ssum[j] += v; ssq[j] += v * v;
            }
            float4* p = (float4*)(g_preact2 + (size_t)m * DDIM + nb0);
            p[0] = make_float4(vals[0], vals[1], vals[2], vals[3]);
            p[1] = make_float4(vals[4], vals[5], vals[6], vals[7]);
        } else if constexpr (MODE == 3) {
            #pragma unroll
            for (int j = 0; j < 8; j++) vals[j] = fmaxf(accf[j] + bia[j], 0.f);
            float4* p = (float4*)(Cout + (size_t)m * DDIM + nb0);
            p[0] = make_float4(vals[0], vals[1], vals[2], vals[3]);
            p[1] = make_float4(vals[4], vals[5], vals[6], vals[7]);
        } else if constexpr (MODE == 4) {
            if (colok) {
                #pragma unroll
                for (int j = 0; j < 8; j++) vals[j] = expf(accf[j] + bia[j]);
                float4* p = (float4*)(Cout + (size_t)m * NDIM + nb0);
                p[0] = make_float4(vals[0], vals[1], vals[2], vals[3]);
                p[1] = make_float4(vals[4], vals[5], vals[6], vals[7]);
            }
        } else {
            if (colok) {
                #pragma unroll
                for (int j = 0; j < 8; j++) vals[j] = accf[j] + bia[j];
                float4* p = (float4*)(Cout + (size_t)m * NDIM + nb0);
                p[0] = make_float4(vals[0], vals[1], vals[2], vals[3]);
                p[1] = make_float4(vals[4], vals[5], vals[6], vals[7]);
            }
        }
    }

    if constexpr (MODE == 2) {
        #pragma unroll
        for (int j = 0; j < 8; j++) {
            atomicAdd(&g_colsum2[nb0 + j], ssum[j]);
            atomicAdd(&g_colsq2[nb0 + j], ssq[j]);
        }
    }
}

// ---------------- launch ----------------
extern "C" void kernel_launch(void* const* d_in, const int* in_sizes, int n_in,
                              void* d_out, int out_size) {
    const float* x_c1 = (const float*)d_in[0];
    const float* x_zc = (const float*)d_in[1];
    const void*  ei   = d_in[2];
    const float* W1  = (const float*)d_in[3];
    const float* b1  = (const float*)d_in[4];
    const float* g1  = (const float*)d_in[5];
    const float* be1 = (const float*)d_in[6];
    const float* W2  = (const float*)d_in[7];
    const float* b2  = (const float*)d_in[8];
    const float* g2  = (const float*)d_in[9];
    const float* be2 = (const float*)d_in[10];
    const float* Wl  = (const float*)d_in[11];
    const float* bl  = (const float*)d_in[12];
    const float* Wr  = (const float*)d_in[13];
    const float* Wc  = (const float*)d_in[14];
    const float* Ws  = (const float*)d_in[15];
    const float* bs  = (const float*)d_in[16];
    const float* Wd  = (const float*)d_in[17];
    const float* bd  = (const float*)d_in[18];
    const float* disp= (const float*)d_in[19];
    const float* Wb  = (const float*)d_in[20];
    const float* bb  = (const float*)d_in[21];

    float* out    = (float*)d_out;
    float* out_zu = out;
    float* out_ps = out_zu + (size_t)NCELLS * DDIM;
    float* out_pr = out_ps + (size_t)NCELLS * GDIM;
    float* out_pd = out_pr + GDIM;
    float* out_bp = out_pd + (size_t)NCELLS * GDIM;

    const int MT = (NCELLS + 127) / 128;  // 391

    k_prep<<<8, 256>>>(disp, out_pr);
    k_rowsum<<<NCELLS, 128>>>(x_c1);
    k_detect<<<1, 32>>>((const int*)ei);

    // GEMM1 tensor attempt (fused BN1 stats) + verification + gated SIMT fallback
    k_wgemm2<1, GDIM, H1DIM, H1DIM, 0><<<dim3(MT, 4), 256>>>(x_c1, nullptr, W1, b1, g_preact1);
    k_check1<<<1, 256>>>(x_c1, W1, b1);
    k_gemm<1, H1DIM, GDIM, true><<<dim3(MT, 4), 256>>>(x_c1, nullptr, W1, nullptr, nullptr, b1, nullptr);
    k_statreset<<<1, H1DIM>>>();       // gated: only if fallback fired
    k_colstats<<<MT, 256>>>();         // gated: only if fallback fired
    k_fin1<<<1, H1DIM>>>(g1, be1);

    // GEMM2 (SIMT): preact2 + BN2 stats
    k_gemm<2, DDIM, H1DIM, false><<<dim3(MT, 1), 256>>>(nullptr, nullptr, W2, nullptr, nullptr, b2, nullptr);
    k_fin2<<<1, DDIM>>>(g2, be2);

    k_zagg<<<((size_t)NCELLS * DDIM + 255) / 256, 256>>>();
    k_scatter<<<(EEDGES * 32) / 256, 256>>>(ei);
    k_invcnt<<<(NCELLS + 255) / 256, 256>>>();

    // GEMM3 (SIMT): z_unique
    k_gemm<3, DDIM, 384, false><<<dim3(MT, 1), 256>>>(x_zc, nullptr, Wl, Wr, Wc, bl, out_zu);
    k_batch<<<(NCELLS + 7) / 8, 256>>>(out_zu, Wb, bb, out_bp);

    // GEMM4/5 tensor attempts + verification + gated SIMT fallbacks
    k_wgemm2<4, H2DIM, GDIM, GDIM, 1><<<dim3(MT, 16), 256>>>(x_zc, out_zu, Ws, bs, out_ps);
    k_wgemm2<4, H2DIM, GDIM, GDIM, 0><<<dim3(MT, 16), 256>>>(x_zc, out_zu, Wd, bd, out_pd);
    k_check45<<<1, 256>>>(x_zc, out_zu, Ws, bs, out_ps);
    k_gemm<4, GDIM, 256, true><<<dim3(MT, 16), 256>>>(x_zc, out_zu, Ws, nullptr, nullptr, bs, out_ps);
    k_gemm<5, GDIM, 256, true><<<dim3(MT, 16), 256>>>(x_zc, out_zu, Wd, nullptr, nullptr, bd, out_pd);
}